// round 15
// baseline (speedup 1.0000x reference)
#include <cuda_runtime.h>
#include <cuda_bf16.h>
#include <cuda_fp16.h>
#include <cstdint>

// ---------------- scratch (no allocations allowed) ----------------
__device__ __half g_Cf[256 * 512];           // c fp16  [r][(n*64+k)]
__device__ __half g_Wtbf[4096 * 512];        // W remap fp16 [(i*64+j)][(n*64+k)]  4 MB
__device__ __half g_bsf[256 * 64];           // bsum fp16 [q][j]
__device__ __half g_S1f[16384 * 64];         // S1 fp16  [(r*64+i)][j]  2 MB
__device__ __half g_A2f[2048 * 64];          // [(n*256+p)][i]  fp16
__device__ __half g_B3f[65536 * 64];         // [(q*256+r)][i]  fp16  8 MB

__device__ __forceinline__ uint32_t pack2h(__half a, __half b) {
    __half2 t;
    t.x = a; t.y = b;
    return *(uint32_t*)&t;
}

// ------------- fused prep: bsum(64) | c(512) | a2(512) | wt(2048) -------------
__global__ void k_prep(const float* __restrict__ b, const float* __restrict__ c,
                       const float* __restrict__ a, const float* __restrict__ W) {
    int blk = blockIdx.x;
    int tid = threadIdx.x;
    if (blk < 64) {
        int idx = blk * 256 + tid;                 // 16384
        int q = idx >> 6, j = idx & 63;
        float s = 0.f;
#pragma unroll
        for (int n = 0; n < 8; n++) s += b[q * 512 + n * 64 + j];
        g_bsf[idx] = __float2half(s);
    } else if (blk < 576) {
        int idx = (blk - 64) * 256 + tid;          // 131072
        g_Cf[idx] = __float2half(c[idx]);
    } else if (blk < 1088) {
        int idx = (blk - 576) * 256 + tid;         // 131072
        int np = idx >> 6, i = idx & 63;
        int n = np >> 8, p = np & 255;
        g_A2f[idx] = __float2half(a[p * 512 + n * 64 + i]);
    } else {
        // W[n][i][j][k] -> Wtbf[(i*64+j)][(n*64+k)], 4 elems/thread, fp16
        int idx = (blk - 1088) * 256 + tid;        // 524288
        int k4 = (idx & 15) * 4;
        int row = idx >> 4;                        // n*4096 + i*64 + j
        int n = row >> 12, ij = row & 4095;
        size_t dst = (size_t)ij * 512 + n * 64 + k4;
        float4 w = *(const float4*)(W + (size_t)row * 64 + k4);
        *(uint2*)(g_Wtbf + dst) = make_uint2(
            pack2h(__float2half(w.x), __float2half(w.y)),
            pack2h(__float2half(w.z), __float2half(w.w)));
    }
}

// ---------------- HMMA core ----------------
__device__ __forceinline__ void mma16816h(float* c, const uint32_t* a, const uint32_t* b) {
    asm volatile(
        "mma.sync.aligned.m16n8k16.row.col.f32.f16.f16.f32 "
        "{%0,%1,%2,%3}, {%4,%5,%6,%7}, {%8,%9}, {%0,%1,%2,%3};"
        : "+f"(c[0]), "+f"(c[1]), "+f"(c[2]), "+f"(c[3])
        : "r"(a[0]), "r"(a[1]), "r"(a[2]), "r"(a[3]), "r"(b[0]), "r"(b[1]));
}

__device__ __forceinline__ void ldsm4(uint32_t& r0, uint32_t& r1, uint32_t& r2, uint32_t& r3,
                                      uint32_t addr) {
    asm volatile("ldmatrix.sync.aligned.m8n8.x4.shared.b16 {%0,%1,%2,%3}, [%4];"
                 : "=r"(r0), "=r"(r1), "=r"(r2), "=r"(r3)
                 : "r"(addr));
}

__device__ __forceinline__ void cpasync16(uint32_t dst, const void* src) {
    asm volatile("cp.async.cg.shared.global [%0], [%1], 16;" :: "r"(dst), "l"(src));
}
__device__ __forceinline__ void cpasync16ca(uint32_t dst, const void* src) {
    asm volatile("cp.async.ca.shared.global [%0], [%1], 16;" :: "r"(dst), "l"(src));
}

static constexpr int LDT = 72;   // padded smem stride (16-bit elems) for K=64 tiles

// single-term fp16 inner loop (verified mapping): MT m-tiles x 4 n-tiles, K=64
template <int MT>
__device__ __forceinline__ void mma_block1(const __half* Af, const __half* Bf,
                                           int wm, int wn, int lane, float (*acc)[4][4]) {
    uint32_t a_b = (uint32_t)__cvta_generic_to_shared(Af);
    uint32_t b_b = (uint32_t)__cvta_generic_to_shared(Bf);
    int tq = lane >> 3, rr = lane & 7;

#pragma unroll
    for (int ks = 0; ks < 4; ks++) {
        int kc = ks * 16;
        uint32_t fb[4][2];
#pragma unroll
        for (int nt2 = 0; nt2 < 2; nt2++) {
            uint32_t off = (uint32_t)(wn + nt2 * 16 + ((tq >> 1) << 3) + rr) * LDT +
                           kc + ((tq & 1) << 3);
            ldsm4(fb[nt2 * 2][0], fb[nt2 * 2][1], fb[nt2 * 2 + 1][0], fb[nt2 * 2 + 1][1],
                  b_b + off * 2);
        }
        uint32_t fa[MT][4];
#pragma unroll
        for (int mt = 0; mt < MT; mt++) {
            uint32_t off = (uint32_t)(wm + mt * 16 + ((tq & 1) << 3) + rr) * LDT +
                           kc + ((tq >> 1) << 3);
            ldsm4(fa[mt][0], fa[mt][1], fa[mt][2], fa[mt][3], a_b + off * 2);
        }
#pragma unroll
        for (int mt = 0; mt < MT; mt++)
#pragma unroll
            for (int nt = 0; nt < 4; nt++)
                mma16816h(acc[mt][nt], fa[mt], fb[nt]);
    }
}

// ---------------- GEMM1 (fp16 HMMA, cp.async double-buffered K loop) -----------
// S1[256x4096] = c[256x512] @ Wtbf^T, tile 64m x 128n, 8 K-stages of 64
static constexpr int G1_A = 64 * LDT;
static constexpr int G1_B = 128 * LDT;
static constexpr int G1_STAGE = G1_A + G1_B;                  // fp16 elems / stage
static constexpr int G1_BYTES = 2 * G1_STAGE * 2;             // 55296 B

__device__ __forceinline__ void g1_load(__half* base, int m0, int n0, int k0, int tid) {
    __half* Af = base;
    __half* Bf = base + G1_A;
    for (int t = tid; t < 512; t += 256) {
        int row = t >> 3, cc = t & 7;
        int d = row * LDT + cc * 8;
        size_t s = (size_t)(m0 + row) * 512 + k0 + cc * 8;
        cpasync16((uint32_t)__cvta_generic_to_shared(Af + d), g_Cf + s);
    }
    for (int t = tid; t < 1024; t += 256) {
        int row = t >> 3, cc = t & 7;
        int d = row * LDT + cc * 8;
        size_t s = (size_t)(n0 + row) * 512 + k0 + cc * 8;
        cpasync16((uint32_t)__cvta_generic_to_shared(Bf + d), g_Wtbf + s);
    }
    asm volatile("cp.async.commit_group;" ::: "memory");
}

__global__ void __launch_bounds__(256, 2) k_gemm1() {
    extern __shared__ __half s1h[];

    int tid = threadIdx.x;
    int wid = tid >> 5, lane = tid & 31;
    int g = lane >> 2, tg = lane & 3;
    int n0 = blockIdx.x * 128;
    int m0 = blockIdx.y * 64;
    int wm = (wid >> 2) * 32, wn = (wid & 3) * 32;

    float acc[2][4][4] = {};

    g1_load(s1h, m0, n0, 0, tid);
    for (int k = 0; k < 8; k++) {
        if (k < 7) {
            g1_load(s1h + ((k + 1) & 1) * G1_STAGE, m0, n0, (k + 1) * 64, tid);
            asm volatile("cp.async.wait_group 1;" ::: "memory");
        } else {
            asm volatile("cp.async.wait_group 0;" ::: "memory");
        }
        __syncthreads();
        __half* buf = s1h + (k & 1) * G1_STAGE;
        mma_block1<2>(buf, buf + G1_A, wm, wn, lane, acc);
        __syncthreads();   // compute done before this buffer is refilled
    }

    // epilogue: fp16 store of S1 (layout [r][ij] == [(r*64+i)][j])
#pragma unroll
    for (int mt = 0; mt < 2; mt++) {
        int row = m0 + wm + mt * 16 + g;
#pragma unroll
        for (int nt = 0; nt < 4; nt++) {
            int col = n0 + wn + nt * 8 + tg * 2;
#pragma unroll
            for (int half = 0; half < 2; half++) {
                int r = row + half * 8;
                __half h0 = __float2half(acc[mt][nt][half * 2 + 0]);
                __half h1 = __float2half(acc[mt][nt][half * 2 + 1]);
                *(uint32_t*)(g_S1f + (size_t)r * 4096 + col) = pack2h(h0, h1);
            }
        }
    }
}

// ---------------- GEMM2 (fp16 HMMA, 1 term): B3[q][m] = bsum @ S1^T -----------
// tile 64q x 128m (512 blocks), one-shot K=64
static constexpr int G2_BYTES = (G1_A + G1_B) * 2;   // 27648

__global__ void __launch_bounds__(256, 3) k_gemm2() {
    extern __shared__ __half sm2[];
    __half* Af = sm2;                 // bsum  64 x 64
    __half* Bf = Af + G1_A;           // S1   128 x 64

    int tid = threadIdx.x;
    int wid = tid >> 5, lane = tid & 31;
    int g = lane >> 2, tg = lane & 3;
    int m0 = blockIdx.x * 128;   // m (S1 row / B3 col)
    int q0 = blockIdx.y * 64;    // q

    for (int t = tid; t < 512; t += 256) {
        int row = t >> 3, cc = t & 7;
        int d = row * LDT + cc * 8;
        *(uint4*)(Af + d) = *(const uint4*)(g_bsf + (size_t)(q0 + row) * 64 + cc * 8);
    }
    for (int t = tid; t < 1024; t += 256) {
        int row = t >> 3, cc = t & 7;
        int d = row * LDT + cc * 8;
        *(uint4*)(Bf + d) = *(const uint4*)(g_S1f + (size_t)(m0 + row) * 64 + cc * 8);
    }
    __syncthreads();

    int wm = (wid >> 2) * 32, wn = (wid & 3) * 32;
    float acc[2][4][4] = {};
    mma_block1<2>(Af, Bf, wm, wn, lane, acc);

    // epilogue: B3[q][m] fp16  (offset q*16384+m == (q*256+r)*64+i)
#pragma unroll
    for (int mt = 0; mt < 2; mt++) {
        int qrow = q0 + wm + mt * 16 + g;
#pragma unroll
        for (int nt = 0; nt < 4; nt++) {
            int col = m0 + wn + nt * 8 + tg * 2;
#pragma unroll
            for (int half = 0; half < 2; half++) {
                int q = qrow + half * 8;
                __half h0 = __float2half(acc[mt][nt][half * 2 + 0]);
                __half h1 = __float2half(acc[mt][nt][half * 2 + 1]);
                *(uint32_t*)(g_B3f + (size_t)q * 16384 + col) = pack2h(h0, h1);
            }
        }
    }
}

// ---------------- GEMM3 (fp16 HMMA): out[2048x65536] = A2 @ B3^T --------------
// R10/R12 structure (verified fastest). Only change: A loads use cp.async.ca
// so co-resident CTAs (same mg, adjacent c0) hit L1 for shared A tiles.
static constexpr int TILE_E = 128 * LDT;
static constexpr int SM3_BYTES = 3 * TILE_E * 2;   // 55296

__device__ __forceinline__ void g3_loadA(__half* dstb, int mgit, int tid) {
    size_t m0 = (size_t)mgit * 128;
    const char* sA = (const char*)(g_A2f + m0 * 64);
    for (int t = tid; t < 1024; t += 256) {
        int row = t >> 3, cc = t & 7;
        uint32_t dst = (uint32_t)__cvta_generic_to_shared(dstb + row * LDT + cc * 8);
        cpasync16ca(dst, sA + t * 16);
    }
    asm volatile("cp.async.commit_group;" ::: "memory");
}

__global__ void __launch_bounds__(256, 3) k_gemm3(float* __restrict__ out) {
    extern __shared__ __half sm3[];
    __half* Bf = sm3;
    __half* Ab0 = Bf + TILE_E;
    __half* Ab1 = Ab0 + TILE_E;

    int tid = threadIdx.x;
    int wid = tid >> 5, lane = tid & 31;
    int g = lane >> 2, tg = lane & 3;
    int tq = lane >> 3, rr = lane & 7;

    int c0 = blockIdx.x * 128;      // column tile (q*256+r)
    int mg = blockIdx.y;            // m-group of 4 m-tiles

    // B tile -> smem (cp.async.cg, group 0)
    {
        const char* sB = (const char*)(g_B3f + (size_t)c0 * 64);
        for (int t = tid; t < 1024; t += 256) {
            int row = t >> 3, cc = t & 7;
            uint32_t dst = (uint32_t)__cvta_generic_to_shared(Bf + row * LDT + cc * 8);
            cpasync16(dst, sB + t * 16);
        }
        asm volatile("cp.async.commit_group;" ::: "memory");
    }
    // A tile 0 prefetch (group 1)
    g3_loadA(Ab0, mg * 4 + 0, tid);

    asm volatile("cp.async.wait_group 1;" ::: "memory");   // B done
    __syncthreads();

    int wm = (wid >> 2) * 64;
    int wn = (wid & 3) * 32;

    // extract B fragments once (register-resident for all 4 iterations)
    uint32_t fb[4][4][2];   // [ks][nt][2]
    {
        uint32_t b_b = (uint32_t)__cvta_generic_to_shared(Bf);
#pragma unroll
        for (int ks = 0; ks < 4; ks++) {
            int kc = ks * 16;
#pragma unroll
            for (int nt2 = 0; nt2 < 2; nt2++) {
                uint32_t off = (uint32_t)(wn + nt2 * 16 + ((tq >> 1) << 3) + rr) * LDT +
                               kc + ((tq & 1) << 3);
                ldsm4(fb[ks][nt2 * 2][0], fb[ks][nt2 * 2][1],
                      fb[ks][nt2 * 2 + 1][0], fb[ks][nt2 * 2 + 1][1], b_b + off * 2);
            }
        }
    }

    for (int it = 0; it < 4; it++) {
        if (it < 3) g3_loadA((it & 1) ? Ab0 : Ab1, mg * 4 + it + 1, tid);
        if (it < 3)
            asm volatile("cp.async.wait_group 1;" ::: "memory");
        else
            asm volatile("cp.async.wait_group 0;" ::: "memory");
        __syncthreads();

        const __half* Af = (it & 1) ? Ab1 : Ab0;
        uint32_t a_b = (uint32_t)__cvta_generic_to_shared(Af);
        size_t m0 = (size_t)(mg * 4 + it) * 128;

#pragma unroll
        for (int mt = 0; mt < 4; mt++) {
            float acc[4][4] = {};
#pragma unroll
            for (int ks = 0; ks < 4; ks++) {
                uint32_t fa[4];
                uint32_t off = (uint32_t)(wm + mt * 16 + ((tq & 1) << 3) + rr) * LDT +
                               ks * 16 + ((tq >> 1) << 3);
                ldsm4(fa[0], fa[1], fa[2], fa[3], a_b + off * 2);
#pragma unroll
                for (int nt = 0; nt < 4; nt++)
                    mma16816h(acc[nt], fa, fb[ks][nt]);
            }
            size_t row = m0 + wm + mt * 16 + g;
            float* o0 = out + row * 65536 + c0;
            float* o1 = o0 + 8 * 65536;
#pragma unroll
            for (int nt = 0; nt < 4; nt++) {
                int col = wn + nt * 8 + tg * 2;
                __stcs((float2*)(o0 + col), make_float2(acc[nt][0], acc[nt][1]));
                __stcs((float2*)(o1 + col), make_float2(acc[nt][2], acc[nt][3]));
            }
        }
        __syncthreads();
    }
}

// ---------------- launch ----------------
extern "C" void kernel_launch(void* const* d_in, const int* in_sizes, int n_in,
                              void* d_out, int out_size) {
    const float* c = (const float*)d_in[0];   // [1,256,8,64]
    const float* b = (const float*)d_in[1];   // [1,256,8,64]
    const float* a = (const float*)d_in[2];   // [1,256,8,64]
    const float* W = (const float*)d_in[3];   // [8,64,64,64]
    float* out = (float*)d_out;               // [1,8,256,256,256]

    cudaFuncSetAttribute(k_gemm1, cudaFuncAttributeMaxDynamicSharedMemorySize, G1_BYTES);
    cudaFuncSetAttribute(k_gemm2, cudaFuncAttributeMaxDynamicSharedMemorySize, G2_BYTES);
    cudaFuncSetAttribute(k_gemm3, cudaFuncAttributeMaxDynamicSharedMemorySize, SM3_BYTES);

    k_prep<<<3136, 256>>>(b, c, a, W);
    k_gemm1<<<dim3(32, 4), 256, G1_BYTES>>>();
    k_gemm2<<<dim3(128, 4), 256, G2_BYTES>>>();
    k_gemm3<<<dim3(512, 4), 256, SM3_BYTES>>>(out);
}

// round 16
// speedup vs baseline: 1.5670x; 1.5670x over previous
#include <cuda_runtime.h>
#include <cuda_bf16.h>
#include <cuda_fp16.h>
#include <cstdint>

// ---------------- scratch (no allocations allowed) ----------------
__device__ __half g_Cf[256 * 512];           // c fp16  [r][(n*64+k)]
__device__ __half g_Wtbf[4096 * 512];        // W remap fp16 [(i*64+j)][(n*64+k)]  4 MB
__device__ __half g_bsf[256 * 64];           // bsum fp16 [q][j]
__device__ __half g_S1f[16384 * 64];         // S1 fp16  [(r*64+i)][j]  2 MB
__device__ __half g_A2f[2048 * 64];          // [(n*256+p)][i]  fp16
__device__ __half g_B3f[65536 * 64];         // [(q*256+r)][i]  fp16  8 MB

__device__ __forceinline__ uint32_t pack2h(__half a, __half b) {
    __half2 t;
    t.x = a; t.y = b;
    return *(uint32_t*)&t;
}

// ------------- fused prep: bsum(64) | c(512) | a2(512) | wt(2048) -------------
__global__ void k_prep(const float* __restrict__ b, const float* __restrict__ c,
                       const float* __restrict__ a, const float* __restrict__ W) {
    int blk = blockIdx.x;
    int tid = threadIdx.x;
    if (blk < 64) {
        int idx = blk * 256 + tid;                 // 16384
        int q = idx >> 6, j = idx & 63;
        float s = 0.f;
#pragma unroll
        for (int n = 0; n < 8; n++) s += b[q * 512 + n * 64 + j];
        g_bsf[idx] = __float2half(s);
    } else if (blk < 576) {
        int idx = (blk - 64) * 256 + tid;          // 131072
        g_Cf[idx] = __float2half(c[idx]);
    } else if (blk < 1088) {
        int idx = (blk - 576) * 256 + tid;         // 131072
        int np = idx >> 6, i = idx & 63;
        int n = np >> 8, p = np & 255;
        g_A2f[idx] = __float2half(a[p * 512 + n * 64 + i]);
    } else {
        // W[n][i][j][k] -> Wtbf[(i*64+j)][(n*64+k)], 4 elems/thread, fp16
        int idx = (blk - 1088) * 256 + tid;        // 524288
        int k4 = (idx & 15) * 4;
        int row = idx >> 4;                        // n*4096 + i*64 + j
        int n = row >> 12, ij = row & 4095;
        size_t dst = (size_t)ij * 512 + n * 64 + k4;
        float4 w = *(const float4*)(W + (size_t)row * 64 + k4);
        *(uint2*)(g_Wtbf + dst) = make_uint2(
            pack2h(__float2half(w.x), __float2half(w.y)),
            pack2h(__float2half(w.z), __float2half(w.w)));
    }
}

// ---------------- HMMA core ----------------
__device__ __forceinline__ void mma16816h(float* c, const uint32_t* a, const uint32_t* b) {
    asm volatile(
        "mma.sync.aligned.m16n8k16.row.col.f32.f16.f16.f32 "
        "{%0,%1,%2,%3}, {%4,%5,%6,%7}, {%8,%9}, {%0,%1,%2,%3};"
        : "+f"(c[0]), "+f"(c[1]), "+f"(c[2]), "+f"(c[3])
        : "r"(a[0]), "r"(a[1]), "r"(a[2]), "r"(a[3]), "r"(b[0]), "r"(b[1]));
}

__device__ __forceinline__ void ldsm4(uint32_t& r0, uint32_t& r1, uint32_t& r2, uint32_t& r3,
                                      uint32_t addr) {
    asm volatile("ldmatrix.sync.aligned.m8n8.x4.shared.b16 {%0,%1,%2,%3}, [%4];"
                 : "=r"(r0), "=r"(r1), "=r"(r2), "=r"(r3)
                 : "r"(addr));
}

__device__ __forceinline__ void cpasync16(uint32_t dst, const void* src) {
    asm volatile("cp.async.cg.shared.global [%0], [%1], 16;" :: "r"(dst), "l"(src));
}

static constexpr int LDT = 72;   // padded smem stride (16-bit elems) for K=64 tiles

// single-term fp16 inner loop (verified mapping): MT m-tiles x 4 n-tiles, K=64
template <int MT>
__device__ __forceinline__ void mma_block1(const __half* Af, const __half* Bf,
                                           int wm, int wn, int lane, float (*acc)[4][4]) {
    uint32_t a_b = (uint32_t)__cvta_generic_to_shared(Af);
    uint32_t b_b = (uint32_t)__cvta_generic_to_shared(Bf);
    int tq = lane >> 3, rr = lane & 7;

#pragma unroll
    for (int ks = 0; ks < 4; ks++) {
        int kc = ks * 16;
        uint32_t fb[4][2];
#pragma unroll
        for (int nt2 = 0; nt2 < 2; nt2++) {
            uint32_t off = (uint32_t)(wn + nt2 * 16 + ((tq >> 1) << 3) + rr) * LDT +
                           kc + ((tq & 1) << 3);
            ldsm4(fb[nt2 * 2][0], fb[nt2 * 2][1], fb[nt2 * 2 + 1][0], fb[nt2 * 2 + 1][1],
                  b_b + off * 2);
        }
        uint32_t fa[MT][4];
#pragma unroll
        for (int mt = 0; mt < MT; mt++) {
            uint32_t off = (uint32_t)(wm + mt * 16 + ((tq & 1) << 3) + rr) * LDT +
                           kc + ((tq >> 1) << 3);
            ldsm4(fa[mt][0], fa[mt][1], fa[mt][2], fa[mt][3], a_b + off * 2);
        }
#pragma unroll
        for (int mt = 0; mt < MT; mt++)
#pragma unroll
            for (int nt = 0; nt < 4; nt++)
                mma16816h(acc[mt][nt], fa[mt], fb[nt]);
    }
}

// ---------------- GEMM1 (fp16 HMMA, cp.async double-buffered K loop) -----------
// S1[256x4096] = c[256x512] @ Wtbf^T, tile 64m x 128n, 8 K-stages of 64
static constexpr int G1_A = 64 * LDT;
static constexpr int G1_B = 128 * LDT;
static constexpr int G1_STAGE = G1_A + G1_B;                  // fp16 elems / stage
static constexpr int G1_BYTES = 2 * G1_STAGE * 2;             // 55296 B

__device__ __forceinline__ void g1_load(__half* base, int m0, int n0, int k0, int tid) {
    __half* Af = base;
    __half* Bf = base + G1_A;
    for (int t = tid; t < 512; t += 256) {
        int row = t >> 3, cc = t & 7;
        int d = row * LDT + cc * 8;
        size_t s = (size_t)(m0 + row) * 512 + k0 + cc * 8;
        cpasync16((uint32_t)__cvta_generic_to_shared(Af + d), g_Cf + s);
    }
    for (int t = tid; t < 1024; t += 256) {
        int row = t >> 3, cc = t & 7;
        int d = row * LDT + cc * 8;
        size_t s = (size_t)(n0 + row) * 512 + k0 + cc * 8;
        cpasync16((uint32_t)__cvta_generic_to_shared(Bf + d), g_Wtbf + s);
    }
    asm volatile("cp.async.commit_group;" ::: "memory");
}

__global__ void __launch_bounds__(256, 2) k_gemm1() {
    extern __shared__ __half s1h[];

    int tid = threadIdx.x;
    int wid = tid >> 5, lane = tid & 31;
    int g = lane >> 2, tg = lane & 3;
    int n0 = blockIdx.x * 128;
    int m0 = blockIdx.y * 64;
    int wm = (wid >> 2) * 32, wn = (wid & 3) * 32;

    float acc[2][4][4] = {};

    g1_load(s1h, m0, n0, 0, tid);
    for (int k = 0; k < 8; k++) {
        if (k < 7) {
            g1_load(s1h + ((k + 1) & 1) * G1_STAGE, m0, n0, (k + 1) * 64, tid);
            asm volatile("cp.async.wait_group 1;" ::: "memory");
        } else {
            asm volatile("cp.async.wait_group 0;" ::: "memory");
        }
        __syncthreads();
        __half* buf = s1h + (k & 1) * G1_STAGE;
        mma_block1<2>(buf, buf + G1_A, wm, wn, lane, acc);
        __syncthreads();   // compute done before this buffer is refilled
    }

    // epilogue: fp16 store of S1 (layout [r][ij] == [(r*64+i)][j])
#pragma unroll
    for (int mt = 0; mt < 2; mt++) {
        int row = m0 + wm + mt * 16 + g;
#pragma unroll
        for (int nt = 0; nt < 4; nt++) {
            int col = n0 + wn + nt * 8 + tg * 2;
#pragma unroll
            for (int half = 0; half < 2; half++) {
                int r = row + half * 8;
                __half h0 = __float2half(acc[mt][nt][half * 2 + 0]);
                __half h1 = __float2half(acc[mt][nt][half * 2 + 1]);
                *(uint32_t*)(g_S1f + (size_t)r * 4096 + col) = pack2h(h0, h1);
            }
        }
    }
}

// ---------------- GEMM2 (fp16 HMMA, 1 term): B3[q][m] = bsum @ S1^T -----------
// tile 64q x 128m (512 blocks), one-shot K=64
static constexpr int G2_BYTES = (G1_A + G1_B) * 2;   // 27648

__global__ void __launch_bounds__(256, 3) k_gemm2() {
    extern __shared__ __half sm2[];
    __half* Af = sm2;                 // bsum  64 x 64
    __half* Bf = Af + G1_A;           // S1   128 x 64

    int tid = threadIdx.x;
    int wid = tid >> 5, lane = tid & 31;
    int g = lane >> 2, tg = lane & 3;
    int m0 = blockIdx.x * 128;   // m (S1 row / B3 col)
    int q0 = blockIdx.y * 64;    // q

    for (int t = tid; t < 512; t += 256) {
        int row = t >> 3, cc = t & 7;
        int d = row * LDT + cc * 8;
        *(uint4*)(Af + d) = *(const uint4*)(g_bsf + (size_t)(q0 + row) * 64 + cc * 8);
    }
    for (int t = tid; t < 1024; t += 256) {
        int row = t >> 3, cc = t & 7;
        int d = row * LDT + cc * 8;
        *(uint4*)(Bf + d) = *(const uint4*)(g_S1f + (size_t)(m0 + row) * 64 + cc * 8);
    }
    __syncthreads();

    int wm = (wid >> 2) * 32, wn = (wid & 3) * 32;
    float acc[2][4][4] = {};
    mma_block1<2>(Af, Bf, wm, wn, lane, acc);

    // epilogue: B3[q][m] fp16  (offset q*16384+m == (q*256+r)*64+i)
#pragma unroll
    for (int mt = 0; mt < 2; mt++) {
        int qrow = q0 + wm + mt * 16 + g;
#pragma unroll
        for (int nt = 0; nt < 4; nt++) {
            int col = m0 + wn + nt * 8 + tg * 2;
#pragma unroll
            for (int half = 0; half < 2; half++) {
                int q = qrow + half * 8;
                __half h0 = __float2half(acc[mt][nt][half * 2 + 0]);
                __half h1 = __float2half(acc[mt][nt][half * 2 + 1]);
                *(uint32_t*)(g_B3f + (size_t)q * 16384 + col) = pack2h(h0, h1);
            }
        }
    }
}

// ---------------- GEMM3 (fp16 HMMA): out[2048x65536] = A2 @ B3^T --------------
// R10/R12/R14 configuration (verified fastest; .cg loads only). DO NOT TOUCH.
static constexpr int TILE_E = 128 * LDT;
static constexpr int SM3_BYTES = 3 * TILE_E * 2;   // 55296

__device__ __forceinline__ void g3_loadA(__half* dstb, int mgit, int tid) {
    size_t m0 = (size_t)mgit * 128;
    const char* sA = (const char*)(g_A2f + m0 * 64);
    for (int t = tid; t < 1024; t += 256) {
        int row = t >> 3, cc = t & 7;
        uint32_t dst = (uint32_t)__cvta_generic_to_shared(dstb + row * LDT + cc * 8);
        cpasync16(dst, sA + t * 16);
    }
    asm volatile("cp.async.commit_group;" ::: "memory");
}

__global__ void __launch_bounds__(256, 3) k_gemm3(float* __restrict__ out) {
    extern __shared__ __half sm3[];
    __half* Bf = sm3;
    __half* Ab0 = Bf + TILE_E;
    __half* Ab1 = Ab0 + TILE_E;

    int tid = threadIdx.x;
    int wid = tid >> 5, lane = tid & 31;
    int g = lane >> 2, tg = lane & 3;
    int tq = lane >> 3, rr = lane & 7;

    int c0 = blockIdx.x * 128;      // column tile (q*256+r)
    int mg = blockIdx.y;            // m-group of 4 m-tiles

    // B tile -> smem (cp.async.cg, group 0)
    {
        const char* sB = (const char*)(g_B3f + (size_t)c0 * 64);
        for (int t = tid; t < 1024; t += 256) {
            int row = t >> 3, cc = t & 7;
            uint32_t dst = (uint32_t)__cvta_generic_to_shared(Bf + row * LDT + cc * 8);
            cpasync16(dst, sB + t * 16);
        }
        asm volatile("cp.async.commit_group;" ::: "memory");
    }
    // A tile 0 prefetch (group 1)
    g3_loadA(Ab0, mg * 4 + 0, tid);

    asm volatile("cp.async.wait_group 1;" ::: "memory");   // B done
    __syncthreads();

    int wm = (wid >> 2) * 64;
    int wn = (wid & 3) * 32;

    // extract B fragments once (register-resident for all 4 iterations)
    uint32_t fb[4][4][2];   // [ks][nt][2]
    {
        uint32_t b_b = (uint32_t)__cvta_generic_to_shared(Bf);
#pragma unroll
        for (int ks = 0; ks < 4; ks++) {
            int kc = ks * 16;
#pragma unroll
            for (int nt2 = 0; nt2 < 2; nt2++) {
                uint32_t off = (uint32_t)(wn + nt2 * 16 + ((tq >> 1) << 3) + rr) * LDT +
                               kc + ((tq & 1) << 3);
                ldsm4(fb[ks][nt2 * 2][0], fb[ks][nt2 * 2][1],
                      fb[ks][nt2 * 2 + 1][0], fb[ks][nt2 * 2 + 1][1], b_b + off * 2);
            }
        }
    }

    for (int it = 0; it < 4; it++) {
        if (it < 3) g3_loadA((it & 1) ? Ab0 : Ab1, mg * 4 + it + 1, tid);
        if (it < 3)
            asm volatile("cp.async.wait_group 1;" ::: "memory");
        else
            asm volatile("cp.async.wait_group 0;" ::: "memory");
        __syncthreads();

        const __half* Af = (it & 1) ? Ab1 : Ab0;
        uint32_t a_b = (uint32_t)__cvta_generic_to_shared(Af);
        size_t m0 = (size_t)(mg * 4 + it) * 128;

#pragma unroll
        for (int mt = 0; mt < 4; mt++) {
            float acc[4][4] = {};
#pragma unroll
            for (int ks = 0; ks < 4; ks++) {
                uint32_t fa[4];
                uint32_t off = (uint32_t)(wm + mt * 16 + ((tq & 1) << 3) + rr) * LDT +
                               ks * 16 + ((tq >> 1) << 3);
                ldsm4(fa[0], fa[1], fa[2], fa[3], a_b + off * 2);
#pragma unroll
                for (int nt = 0; nt < 4; nt++)
                    mma16816h(acc[nt], fa, fb[ks][nt]);
            }
            size_t row = m0 + wm + mt * 16 + g;
            float* o0 = out + row * 65536 + c0;
            float* o1 = o0 + 8 * 65536;
#pragma unroll
            for (int nt = 0; nt < 4; nt++) {
                int col = wn + nt * 8 + tg * 2;
                __stcs((float2*)(o0 + col), make_float2(acc[nt][0], acc[nt][1]));
                __stcs((float2*)(o1 + col), make_float2(acc[nt][2], acc[nt][3]));
            }
        }
        __syncthreads();
    }
}

// ---------------- launch ----------------
extern "C" void kernel_launch(void* const* d_in, const int* in_sizes, int n_in,
                              void* d_out, int out_size) {
    const float* c = (const float*)d_in[0];   // [1,256,8,64]
    const float* b = (const float*)d_in[1];   // [1,256,8,64]
    const float* a = (const float*)d_in[2];   // [1,256,8,64]
    const float* W = (const float*)d_in[3];   // [8,64,64,64]
    float* out = (float*)d_out;               // [1,8,256,256,256]

    cudaFuncSetAttribute(k_gemm1, cudaFuncAttributeMaxDynamicSharedMemorySize, G1_BYTES);
    cudaFuncSetAttribute(k_gemm2, cudaFuncAttributeMaxDynamicSharedMemorySize, G2_BYTES);
    cudaFuncSetAttribute(k_gemm3, cudaFuncAttributeMaxDynamicSharedMemorySize, SM3_BYTES);

    k_prep<<<3136, 256>>>(b, c, a, W);
    k_gemm1<<<dim3(32, 4), 256, G1_BYTES>>>();
    k_gemm2<<<dim3(128, 4), 256, G2_BYTES>>>();
    k_gemm3<<<dim3(512, 4), 256, SM3_BYTES>>>(out);
}